// round 1
// baseline (speedup 1.0000x reference)
#include <cuda_runtime.h>
#include <math.h>

// Problem constants
#define SEQ   2048
#define ND    128      // node_dim
#define NH    24       // 3*H total heads
#define CD    32       // channels per head (k/q)
// k/q row stride = 24*32 = 768 ; val row stride = 24*128 = 3072

// ---------------- scratch (device globals; no allocation allowed) ----------------
__device__ float g_k   [SEQ * NH * CD];     // [s][h][c]  6.3 MB
__device__ float g_q   [SEQ * NH * CD];     // [s][h][c]  6.3 MB
__device__ float g_val [SEQ * NH * ND];     // [s][h][d]  25 MB
__device__ float g_part[NH  * SEQ * ND];    // [h][i][d]  25 MB

// ============================================================================
// Kernel 1: k/q projections from nodes (128), pos_feat (6), rot (4)
// Block = 16 rows, 256 threads. Output layout: o = src*512 + h_local*64 + c64.
// ============================================================================
__global__ void proj_kq_kernel(const float* __restrict__ nodes,
                               const float* __restrict__ pos,
                               const float* __restrict__ rot,
                               const float* __restrict__ w_nkq,
                               const float* __restrict__ b_nkq,
                               const float* __restrict__ w_pkq,
                               const float* __restrict__ b_pkq,
                               const float* __restrict__ w_rkq)
{
    __shared__ float feat[16][140];   // 128 nodes + 3 cos + 3 sin + 4 rot
    __shared__ float ws[64][129];     // weight chunk, odd pad -> conflict-free
    int t = threadIdx.x;
    int row0 = blockIdx.x * 16;

    for (int idx = t; idx < 16 * 128; idx += 256) {
        int r = idx >> 7, d = idx & 127;
        feat[r][d] = nodes[(row0 + r) * 128 + d];
    }
    if (t < 16) {
        int r = t;
        #pragma unroll
        for (int kk = 0; kk < 3; kk++) {
            float p = pos[(row0 + r) * 3 + kk];
            float sn, cs;
            sincosf(6.28318530717958647692f * p, &sn, &cs);
            feat[r][128 + kk] = cs;       // cos first
            feat[r][131 + kk] = sn;       // then sin
        }
        #pragma unroll
        for (int kk = 0; kk < 4; kk++)
            feat[r][134 + kk] = rot[(row0 + r) * 4 + kk];
    }
    __syncthreads();

    int o_local = t & 63;
    int rbase   = (t >> 6) * 4;

    for (int c = 0; c < 24; c++) {            // 24 chunks of 64 outputs = 1536
        int oglob0  = c * 64;
        int src     = oglob0 >> 9;            // 0=nodes, 1=pos, 2=rot
        int within0 = oglob0 & 511;
        const float* W; const float* B; int Din, Doff;
        if (src == 0)      { W = w_nkq; B = b_nkq; Din = 128; Doff = 0;   }
        else if (src == 1) { W = w_pkq; B = b_pkq; Din = 6;   Doff = 128; }
        else               { W = w_rkq; B = 0;     Din = 4;   Doff = 134; }

        for (int idx = t; idx < 64 * Din; idx += 256) {
            int oo = idx / Din;
            int d  = idx - oo * Din;
            ws[oo][d] = W[(within0 + oo) * Din + d];
        }
        __syncthreads();

        float a0 = 0.f, a1 = 0.f, a2 = 0.f, a3 = 0.f;
        for (int d = 0; d < Din; d++) {
            float w = ws[o_local][d];
            a0 += w * feat[rbase + 0][Doff + d];
            a1 += w * feat[rbase + 1][Doff + d];
            a2 += w * feat[rbase + 2][Doff + d];
            a3 += w * feat[rbase + 3][Doff + d];
        }
        int within = within0 + o_local;
        if (B) { float bb = B[within]; a0 += bb; a1 += bb; a2 += bb; a3 += bb; }

        int hl = within >> 6, c64 = within & 63;
        int head = src * 8 + hl;
        float av[4] = {a0, a1, a2, a3};
        if (c64 < 32) {
            #pragma unroll
            for (int r = 0; r < 4; r++)
                g_k[(row0 + rbase + r) * (NH * CD) + head * CD + c64] = av[r];
        } else {
            #pragma unroll
            for (int r = 0; r < 4; r++)
                g_q[(row0 + rbase + r) * (NH * CD) + head * CD + (c64 - 32)] = av[r];
        }
        __syncthreads();
    }
}

// ============================================================================
// Kernel 2: values GEMM  val[s][o] = nodes[s]·w_values[o] + b  (o = h*128+d)
// Block = 16 rows, 256 threads, 48 chunks of 64 outputs.
// ============================================================================
__global__ void proj_val_kernel(const float* __restrict__ nodes,
                                const float* __restrict__ w_val,
                                const float* __restrict__ b_val)
{
    __shared__ float feat[16][130];
    __shared__ float ws[64][129];
    int t = threadIdx.x;
    int row0 = blockIdx.x * 16;

    for (int idx = t; idx < 16 * 128; idx += 256) {
        int r = idx >> 7, d = idx & 127;
        feat[r][d] = nodes[(row0 + r) * 128 + d];
    }
    __syncthreads();

    int o_local = t & 63;
    int rbase   = (t >> 6) * 4;

    for (int c = 0; c < 48; c++) {
        int o0 = c * 64;
        for (int idx = t; idx < 8192; idx += 256) {
            int oo = idx >> 7, d = idx & 127;
            ws[oo][d] = w_val[(o0 + oo) * 128 + d];
        }
        __syncthreads();

        float a0 = 0.f, a1 = 0.f, a2 = 0.f, a3 = 0.f;
        #pragma unroll 8
        for (int d = 0; d < 128; d++) {
            float w = ws[o_local][d];
            a0 += w * feat[rbase + 0][d];
            a1 += w * feat[rbase + 1][d];
            a2 += w * feat[rbase + 2][d];
            a3 += w * feat[rbase + 3][d];
        }
        int og = o0 + o_local;
        float bb = b_val[og];
        g_val[(row0 + rbase + 0) * (NH * ND) + og] = a0 + bb;
        g_val[(row0 + rbase + 1) * (NH * ND) + og] = a1 + bb;
        g_val[(row0 + rbase + 2) * (NH * ND) + og] = a2 + bb;
        g_val[(row0 + rbase + 3) * (NH * ND) + og] = a3 + bb;
        __syncthreads();
    }
}

// ============================================================================
// Kernel 3: flash attention per (head, 64-row i-tile). 24 x 32 = 768 CTAs.
// s[i,j] = k_i · q_j  (squared for heads >= 16); online softmax over j;
// acc[i,d] += p * val[j,h,d].  Epilogue: g_part[h][i][d] = acc / l.
// ============================================================================
__global__ void flash_head_kernel()
{
    __shared__ float sk[64][33];
    __shared__ float sq[32][33];
    __shared__ float sv[32][128];
    __shared__ float sp[64][33];
    __shared__ float sm[64], sl[64], sfac[64];

    int t  = threadIdx.x;
    int h  = blockIdx.x;             // 0..23
    int i0 = blockIdx.y * 64;        // i-tile base
    bool rot_head = (h >= 16);

    for (int idx = t; idx < 2048; idx += 256) {
        int i = idx >> 5, cc = idx & 31;
        sk[i][cc] = g_k[(i0 + i) * (NH * CD) + h * CD + cc];
    }
    if (t < 64) { sm[t] = -3.0e38f; sl[t] = 0.f; }

    float acc[4][8];
    #pragma unroll
    for (int r = 0; r < 4; r++)
        #pragma unroll
        for (int n = 0; n < 8; n++) acc[r][n] = 0.f;

    int ig = t >> 4;      // 0..15 -> rows ig*4..ig*4+3
    int dg = t & 15;      // 0..15 -> cols dg*8..dg*8+7
    __syncthreads();

    for (int j0 = 0; j0 < SEQ; j0 += 32) {
        // stage q, v tiles
        for (int idx = t; idx < 1024; idx += 256) {
            int jj = idx >> 5, cc = idx & 31;
            sq[jj][cc] = g_q[(j0 + jj) * (NH * CD) + h * CD + cc];
        }
        for (int idx = t; idx < 1024; idx += 256) {
            int jj = idx >> 5, d4 = idx & 31;
            ((float4*)sv[jj])[d4] =
                ((const float4*)(g_val + (size_t)(j0 + jj) * (NH * ND) + h * ND))[d4];
        }
        __syncthreads();

        // Phase A: logits tile -> sp
        {
            int ia = t >> 2;
            int jb = (t & 3) * 8;
            float kr[32];
            #pragma unroll
            for (int cc = 0; cc < 32; cc++) kr[cc] = sk[ia][cc];
            #pragma unroll
            for (int n = 0; n < 8; n++) {
                float s = 0.f;
                #pragma unroll
                for (int cc = 0; cc < 32; cc++) s += kr[cc] * sq[jb + n][cc];
                if (rot_head) s = s * s;
                sp[ia][jb + n] = s;
            }
        }
        __syncthreads();

        // Phase B: per-row online softmax stats; sp <- exp(s - m_new)
        if (t < 64) {
            float mo = sm[t], mx = mo;
            #pragma unroll
            for (int jj = 0; jj < 32; jj++) mx = fmaxf(mx, sp[t][jj]);
            float fac = __expf(mo - mx);
            float sum = 0.f;
            #pragma unroll
            for (int jj = 0; jj < 32; jj++) {
                float p = __expf(sp[t][jj] - mx);
                sp[t][jj] = p;
                sum += p;
            }
            sl[t] = sl[t] * fac + sum;
            sm[t] = mx;
            sfac[t] = fac;
        }
        __syncthreads();

        // Phase C: rescale + rank-32 update of acc
        #pragma unroll
        for (int r = 0; r < 4; r++) {
            float f = sfac[ig * 4 + r];
            #pragma unroll
            for (int n = 0; n < 8; n++) acc[r][n] *= f;
        }
        for (int jj = 0; jj < 32; jj++) {
            float4 va = *(const float4*)&sv[jj][dg * 8];
            float4 vb = *(const float4*)&sv[jj][dg * 8 + 4];
            #pragma unroll
            for (int r = 0; r < 4; r++) {
                float p = sp[ig * 4 + r][jj];
                acc[r][0] += p * va.x; acc[r][1] += p * va.y;
                acc[r][2] += p * va.z; acc[r][3] += p * va.w;
                acc[r][4] += p * vb.x; acc[r][5] += p * vb.y;
                acc[r][6] += p * vb.z; acc[r][7] += p * vb.w;
            }
        }
        __syncthreads();
    }

    // epilogue: normalize and write per-head partial
    #pragma unroll
    for (int r = 0; r < 4; r++) {
        int i = i0 + ig * 4 + r;
        float rl = 1.f / sl[ig * 4 + r];
        #pragma unroll
        for (int n = 0; n < 8; n++)
            g_part[((size_t)h * SEQ + i) * ND + dg * 8 + n] = acc[r][n] * rl;
    }
}

// ============================================================================
// Kernel 4: sum 24 head partials -> out [2048, 128]
// ============================================================================
__global__ void reduce_kernel(float* __restrict__ out)
{
    int idx = blockIdx.x * 256 + threadIdx.x;    // < 2048*128
    float s = 0.f;
    #pragma unroll
    for (int h = 0; h < NH; h++)
        s += g_part[(size_t)h * (SEQ * ND) + idx];
    out[idx] = s;
}

// ============================================================================
extern "C" void kernel_launch(void* const* d_in, const int* in_sizes, int n_in,
                              void* d_out, int out_size)
{
    const float* nodes = (const float*)d_in[0];
    const float* pos   = (const float*)d_in[1];
    const float* rot   = (const float*)d_in[2];
    const float* w_nkq = (const float*)d_in[3];
    const float* b_nkq = (const float*)d_in[4];
    const float* w_pkq = (const float*)d_in[5];
    const float* b_pkq = (const float*)d_in[6];
    const float* w_rkq = (const float*)d_in[7];
    const float* w_val = (const float*)d_in[8];
    const float* b_val = (const float*)d_in[9];
    float* out = (float*)d_out;

    proj_kq_kernel<<<SEQ / 16, 256>>>(nodes, pos, rot, w_nkq, b_nkq,
                                      w_pkq, b_pkq, w_rkq);
    proj_val_kernel<<<SEQ / 16, 256>>>(nodes, w_val, b_val);
    dim3 g3(NH, SEQ / 64);
    flash_head_kernel<<<g3, 256>>>();
    reduce_kernel<<<(SEQ * ND) / 256, 256>>>(out);
}

// round 3
// speedup vs baseline: 1.8190x; 1.8190x over previous
#include <cuda_runtime.h>
#include <math.h>
#include <stdint.h>

// Problem constants
#define SEQ   2048
#define ND    128      // node_dim
#define NH    24       // 3*H total heads
#define CD    32       // channels per head (k/q)

// ---------------- scratch (device globals; no allocation allowed) ----------------
__device__ float g_k   [SEQ * NH * CD];     // [s][h][c]  6.3 MB
__device__ float g_q   [SEQ * NH * CD];     // [s][h][c]  6.3 MB
__device__ float g_val [SEQ * NH * ND];     // [s][h][d]  25 MB
__device__ float g_part[NH  * SEQ * ND];    // [h][i][d]  25 MB

// ---------------- helpers ----------------
__device__ __forceinline__ float tf32r(float x) {
    uint32_t u;
    asm("cvt.rna.tf32.f32 %0, %1;" : "=r"(u) : "f"(x));
    return __uint_as_float(u);
}

__device__ __forceinline__ void mma_tf32(float c[4],
                                         uint32_t a0, uint32_t a1, uint32_t a2, uint32_t a3,
                                         uint32_t b0, uint32_t b1) {
    asm volatile(
        "mma.sync.aligned.m16n8k8.row.col.f32.tf32.tf32.f32 "
        "{%0,%1,%2,%3}, {%4,%5,%6,%7}, {%8,%9}, {%0,%1,%2,%3};"
        : "+f"(c[0]), "+f"(c[1]), "+f"(c[2]), "+f"(c[3])
        : "r"(a0), "r"(a1), "r"(a2), "r"(a3), "r"(b0), "r"(b1));
}

// ============================================================================
// Kernel 1: k/q projections from nodes (128), pos_feat (6), rot (4)
// ============================================================================
__global__ void proj_kq_kernel(const float* __restrict__ nodes,
                               const float* __restrict__ pos,
                               const float* __restrict__ rot,
                               const float* __restrict__ w_nkq,
                               const float* __restrict__ b_nkq,
                               const float* __restrict__ w_pkq,
                               const float* __restrict__ b_pkq,
                               const float* __restrict__ w_rkq)
{
    __shared__ float feat[16][140];
    __shared__ float ws[64][129];
    int t = threadIdx.x;
    int row0 = blockIdx.x * 16;

    for (int idx = t; idx < 16 * 128; idx += 256) {
        int r = idx >> 7, d = idx & 127;
        feat[r][d] = nodes[(row0 + r) * 128 + d];
    }
    if (t < 16) {
        int r = t;
        #pragma unroll
        for (int kk = 0; kk < 3; kk++) {
            float p = pos[(row0 + r) * 3 + kk];
            float sn, cs;
            sincosf(6.28318530717958647692f * p, &sn, &cs);
            feat[r][128 + kk] = cs;
            feat[r][131 + kk] = sn;
        }
        #pragma unroll
        for (int kk = 0; kk < 4; kk++)
            feat[r][134 + kk] = rot[(row0 + r) * 4 + kk];
    }
    __syncthreads();

    int o_local = t & 63;
    int rbase   = (t >> 6) * 4;

    for (int c = 0; c < 24; c++) {
        int oglob0  = c * 64;
        int src     = oglob0 >> 9;
        int within0 = oglob0 & 511;
        const float* W; const float* B; int Din, Doff;
        if (src == 0)      { W = w_nkq; B = b_nkq; Din = 128; Doff = 0;   }
        else if (src == 1) { W = w_pkq; B = b_pkq; Din = 6;   Doff = 128; }
        else               { W = w_rkq; B = 0;     Din = 4;   Doff = 134; }

        for (int idx = t; idx < 64 * Din; idx += 256) {
            int oo = idx / Din;
            int d  = idx - oo * Din;
            ws[oo][d] = W[(within0 + oo) * Din + d];
        }
        __syncthreads();

        float a0 = 0.f, a1 = 0.f, a2 = 0.f, a3 = 0.f;
        for (int d = 0; d < Din; d++) {
            float w = ws[o_local][d];
            a0 += w * feat[rbase + 0][Doff + d];
            a1 += w * feat[rbase + 1][Doff + d];
            a2 += w * feat[rbase + 2][Doff + d];
            a3 += w * feat[rbase + 3][Doff + d];
        }
        int within = within0 + o_local;
        if (B) { float bb = B[within]; a0 += bb; a1 += bb; a2 += bb; a3 += bb; }

        int hl = within >> 6, c64 = within & 63;
        int head = src * 8 + hl;
        float av[4] = {a0, a1, a2, a3};
        if (c64 < 32) {
            #pragma unroll
            for (int r = 0; r < 4; r++)
                g_k[(row0 + rbase + r) * (NH * CD) + head * CD + c64] = av[r];
        } else {
            #pragma unroll
            for (int r = 0; r < 4; r++)
                g_q[(row0 + rbase + r) * (NH * CD) + head * CD + (c64 - 32)] = av[r];
        }
        __syncthreads();
    }
}

// ============================================================================
// Kernel 2: values GEMM
// ============================================================================
__global__ void proj_val_kernel(const float* __restrict__ nodes,
                                const float* __restrict__ w_val,
                                const float* __restrict__ b_val)
{
    __shared__ float feat[16][130];
    __shared__ float ws[64][129];
    int t = threadIdx.x;
    int row0 = blockIdx.x * 16;

    for (int idx = t; idx < 16 * 128; idx += 256) {
        int r = idx >> 7, d = idx & 127;
        feat[r][d] = nodes[(row0 + r) * 128 + d];
    }
    __syncthreads();

    int o_local = t & 63;
    int rbase   = (t >> 6) * 4;

    for (int c = 0; c < 48; c++) {
        int o0 = c * 64;
        for (int idx = t; idx < 8192; idx += 256) {
            int oo = idx >> 7, d = idx & 127;
            ws[oo][d] = w_val[(o0 + oo) * 128 + d];
        }
        __syncthreads();

        float a0 = 0.f, a1 = 0.f, a2 = 0.f, a3 = 0.f;
        #pragma unroll 8
        for (int d = 0; d < 128; d++) {
            float w = ws[o_local][d];
            a0 += w * feat[rbase + 0][d];
            a1 += w * feat[rbase + 1][d];
            a2 += w * feat[rbase + 2][d];
            a3 += w * feat[rbase + 3][d];
        }
        int og = o0 + o_local;
        float bb = b_val[og];
        g_val[(row0 + rbase + 0) * (NH * ND) + og] = a0 + bb;
        g_val[(row0 + rbase + 1) * (NH * ND) + og] = a1 + bb;
        g_val[(row0 + rbase + 2) * (NH * ND) + og] = a2 + bb;
        g_val[(row0 + rbase + 3) * (NH * ND) + og] = a3 + bb;
        __syncthreads();
    }
}

// ============================================================================
// Kernel 3: flash attention per (head, 64-i-tile), mma.sync tf32.
// MMA1 (logits) uses 3xTF32 (hi/lo split) for ~fp32 logit precision; the
// squared rot-head logits + exp make logit precision the error bottleneck.
// MMA2 (P@V) is 1xTF32 (error ~1e-4, under the 1e-3 budget).
// grid = (24, 32), block = 256 (8 warps).
// ============================================================================
__global__ void __launch_bounds__(256, 2) flash_head_mma_kernel()
{
    __shared__ float sk[64][36];     // fp32 unrounded K
    __shared__ float sq[32][36];     // fp32 unrounded Q
    __shared__ float sv[32][132];    // tf32-rounded V
    __shared__ float sp[64][36];     // logits, then tf32-rounded probabilities
    __shared__ float sm[64], sl[64], sfac[64];

    const int t    = threadIdx.x;
    const int lane = t & 31;
    const int w    = t >> 5;
    const int gid  = lane >> 2;   // 0..7
    const int tig  = lane & 3;    // 0..3
    const int iw   = w >> 1;      // 0..3 : i block of 16 rows
    const int dblk = w & 1;       // 0..1 : d block of 64 cols

    const int h  = blockIdx.x;
    const int i0 = blockIdx.y * 64;
    const bool rot_head = (h >= 16);

    for (int idx = t; idx < 64 * 32; idx += 256) {
        int i = idx >> 5, cc = idx & 31;
        sk[i][cc] = g_k[(i0 + i) * (NH * CD) + h * CD + cc];
    }
    if (t < 64) { sm[t] = -1.0e30f; sl[t] = 0.f; }
    __syncthreads();

    // K fragments, hi/lo split (reused across all j-tiles)
    uint32_t kh[4][4], kl[4][4];
    #pragma unroll
    for (int ks = 0; ks < 4; ks++) {
        float f0 = sk[iw * 16 + gid    ][ks * 8 + tig    ];
        float f1 = sk[iw * 16 + gid + 8][ks * 8 + tig    ];
        float f2 = sk[iw * 16 + gid    ][ks * 8 + tig + 4];
        float f3 = sk[iw * 16 + gid + 8][ks * 8 + tig + 4];
        float h0 = tf32r(f0), h1 = tf32r(f1), h2 = tf32r(f2), h3 = tf32r(f3);
        kh[ks][0] = __float_as_uint(h0); kl[ks][0] = __float_as_uint(tf32r(f0 - h0));
        kh[ks][1] = __float_as_uint(h1); kl[ks][1] = __float_as_uint(tf32r(f1 - h1));
        kh[ks][2] = __float_as_uint(h2); kl[ks][2] = __float_as_uint(tf32r(f2 - h2));
        kh[ks][3] = __float_as_uint(h3); kl[ks][3] = __float_as_uint(tf32r(f3 - h3));
    }

    float acc[8][4];
    #pragma unroll
    for (int nt = 0; nt < 8; nt++)
        #pragma unroll
        for (int r = 0; r < 4; r++) acc[nt][r] = 0.f;

    for (int j0 = 0; j0 < SEQ; j0 += 32) {
        // ---- stage Q (fp32) and V (tf32) tiles ----
        for (int idx = t; idx < 32 * 32; idx += 256) {
            int jj = idx >> 5, cc = idx & 31;
            sq[jj][cc] = g_q[(j0 + jj) * (NH * CD) + h * CD + cc];
        }
        for (int idx = t; idx < 1024; idx += 256) {
            int jj = idx >> 5, d4 = idx & 31;
            float4 v = ((const float4*)(g_val + (size_t)(j0 + jj) * (NH * ND) + h * ND))[d4];
            sv[jj][d4 * 4 + 0] = tf32r(v.x);
            sv[jj][d4 * 4 + 1] = tf32r(v.y);
            sv[jj][d4 * 4 + 2] = tf32r(v.z);
            sv[jj][d4 * 4 + 3] = tf32r(v.w);
        }
        __syncthreads();

        // ---- MMA1 (3xTF32): S[64 x 32] = K @ Q^T ----
        #pragma unroll
        for (int s = 0; s < 2; s++) {
            int jb = dblk * 2 + s;   // 0..3
            float d[4] = {0.f, 0.f, 0.f, 0.f};
            #pragma unroll
            for (int ks = 0; ks < 4; ks++) {
                float q0 = sq[jb * 8 + gid][ks * 8 + tig    ];
                float q1 = sq[jb * 8 + gid][ks * 8 + tig + 4];
                float q0h = tf32r(q0), q1h = tf32r(q1);
                uint32_t b0h = __float_as_uint(q0h);
                uint32_t b1h = __float_as_uint(q1h);
                uint32_t b0l = __float_as_uint(tf32r(q0 - q0h));
                uint32_t b1l = __float_as_uint(tf32r(q1 - q1h));
                mma_tf32(d, kh[ks][0], kh[ks][1], kh[ks][2], kh[ks][3], b0h, b1h);
                mma_tf32(d, kh[ks][0], kh[ks][1], kh[ks][2], kh[ks][3], b0l, b1l);
                mma_tf32(d, kl[ks][0], kl[ks][1], kl[ks][2], kl[ks][3], b0h, b1h);
            }
            sp[iw * 16 + gid    ][jb * 8 + 2 * tig    ] = d[0];
            sp[iw * 16 + gid    ][jb * 8 + 2 * tig + 1] = d[1];
            sp[iw * 16 + gid + 8][jb * 8 + 2 * tig    ] = d[2];
            sp[iw * 16 + gid + 8][jb * 8 + 2 * tig + 1] = d[3];
        }
        __syncthreads();

        // ---- online softmax: thread t handles row t>>2, 8 cols ----
        {
            int row = t >> 2;
            int c0  = (t & 3) * 8;
            float e[8];
            #pragma unroll
            for (int jj = 0; jj < 8; jj++) {
                float s = sp[row][c0 + jj];
                if (rot_head) s = s * s;
                e[jj] = s;
            }
            float mx8 = e[0];
            #pragma unroll
            for (int jj = 1; jj < 8; jj++) mx8 = fmaxf(mx8, e[jj]);
            mx8 = fmaxf(mx8, __shfl_xor_sync(0xffffffffu, mx8, 1));
            mx8 = fmaxf(mx8, __shfl_xor_sync(0xffffffffu, mx8, 2));
            float mo  = sm[row];
            float mx  = fmaxf(mo, mx8);
            float sum = 0.f;
            #pragma unroll
            for (int jj = 0; jj < 8; jj++) {
                float p = __expf(e[jj] - mx);
                sum += p;
                sp[row][c0 + jj] = tf32r(p);
            }
            sum += __shfl_xor_sync(0xffffffffu, sum, 1);
            sum += __shfl_xor_sync(0xffffffffu, sum, 2);
            if ((t & 3) == 0) {
                float fac = __expf(mo - mx);
                sl[row]   = sl[row] * fac + sum;
                sm[row]   = mx;
                sfac[row] = fac;
            }
        }
        __syncthreads();

        // ---- rescale accumulators ----
        {
            float f0 = sfac[iw * 16 + gid];
            float f1 = sfac[iw * 16 + gid + 8];
            #pragma unroll
            for (int nt = 0; nt < 8; nt++) {
                acc[nt][0] *= f0; acc[nt][1] *= f0;
                acc[nt][2] *= f1; acc[nt][3] *= f1;
            }
        }

        // ---- MMA2 (1xTF32): out[16 x 64] += P[16 x 32] @ V[32 x 64] ----
        #pragma unroll
        for (int ks = 0; ks < 4; ks++) {
            uint32_t a0 = __float_as_uint(sp[iw * 16 + gid    ][ks * 8 + tig    ]);
            uint32_t a1 = __float_as_uint(sp[iw * 16 + gid + 8][ks * 8 + tig    ]);
            uint32_t a2 = __float_as_uint(sp[iw * 16 + gid    ][ks * 8 + tig + 4]);
            uint32_t a3 = __float_as_uint(sp[iw * 16 + gid + 8][ks * 8 + tig + 4]);
            #pragma unroll
            for (int nt = 0; nt < 8; nt++) {
                int col = dblk * 64 + nt * 8 + gid;
                uint32_t b0 = __float_as_uint(sv[ks * 8 + tig    ][col]);
                uint32_t b1 = __float_as_uint(sv[ks * 8 + tig + 4][col]);
                mma_tf32(acc[nt], a0, a1, a2, a3, b0, b1);
            }
        }
        __syncthreads();
    }

    // ---- epilogue: normalize, write per-head partial ----
    {
        int r0 = iw * 16 + gid;
        int r1 = r0 + 8;
        float rl0 = 1.f / sl[r0];
        float rl1 = 1.f / sl[r1];
        #pragma unroll
        for (int nt = 0; nt < 8; nt++) {
            int col = dblk * 64 + nt * 8 + 2 * tig;
            float2 v0 = make_float2(acc[nt][0] * rl0, acc[nt][1] * rl0);
            float2 v1 = make_float2(acc[nt][2] * rl1, acc[nt][3] * rl1);
            *(float2*)&g_part[((size_t)h * SEQ + i0 + r0) * ND + col] = v0;
            *(float2*)&g_part[((size_t)h * SEQ + i0 + r1) * ND + col] = v1;
        }
    }
}

// ============================================================================
// Kernel 4: sum 24 head partials -> out [2048, 128]
// ============================================================================
__global__ void reduce_kernel(float* __restrict__ out)
{
    int idx = blockIdx.x * 256 + threadIdx.x;
    float s = 0.f;
    #pragma unroll
    for (int h = 0; h < NH; h++)
        s += g_part[(size_t)h * (SEQ * ND) + idx];
    out[idx] = s;
}

// ============================================================================
extern "C" void kernel_launch(void* const* d_in, const int* in_sizes, int n_in,
                              void* d_out, int out_size)
{
    const float* nodes = (const float*)d_in[0];
    const float* pos   = (const float*)d_in[1];
    const float* rot   = (const float*)d_in[2];
    const float* w_nkq = (const float*)d_in[3];
    const float* b_nkq = (const float*)d_in[4];
    const float* w_pkq = (const float*)d_in[5];
    const float* b_pkq = (const float*)d_in[6];
    const float* w_rkq = (const float*)d_in[7];
    const float* w_val = (const float*)d_in[8];
    const float* b_val = (const float*)d_in[9];
    float* out = (float*)d_out;

    proj_kq_kernel<<<SEQ / 16, 256>>>(nodes, pos, rot, w_nkq, b_nkq,
                                      w_pkq, b_pkq, w_rkq);
    proj_val_kernel<<<SEQ / 16, 256>>>(nodes, w_val, b_val);
    dim3 g3(NH, SEQ / 64);
    flash_head_mma_kernel<<<g3, 256>>>();
    reduce_kernel<<<(SEQ * ND) / 256, 256>>>(out);
}

// round 5
// speedup vs baseline: 3.0718x; 1.6888x over previous
#include <cuda_runtime.h>
#include <math.h>
#include <stdint.h>

// Problem constants
#define SEQ   2048
#define ND    128      // node_dim
#define NH    24       // 3*H total heads
#define CD    32       // channels per head (k/q)
#define KQSTR (NH*CD)  // 768
#define VSTR  (NH*ND)  // 3072

// ---------------- scratch (device globals) ----------------
__device__ float g_kh  [SEQ * NH * CD];
__device__ float g_kl  [SEQ * NH * CD];
__device__ float g_qh  [SEQ * NH * CD];
__device__ float g_ql  [SEQ * NH * CD];
__device__ float g_val [SEQ * NH * ND];     // tf32-rounded at store
__device__ float g_part[NH  * SEQ * ND];

// ---------------- helpers ----------------
__device__ __forceinline__ float tf32r(float x) {
    uint32_t u;
    asm("cvt.rna.tf32.f32 %0, %1;" : "=r"(u) : "f"(x));
    return __uint_as_float(u);
}

__device__ __forceinline__ void mma_tf32(float c[4],
                                         uint32_t a0, uint32_t a1, uint32_t a2, uint32_t a3,
                                         uint32_t b0, uint32_t b1) {
    asm volatile(
        "mma.sync.aligned.m16n8k8.row.col.f32.tf32.tf32.f32 "
        "{%0,%1,%2,%3}, {%4,%5,%6,%7}, {%8,%9}, {%0,%1,%2,%3};"
        : "+f"(c[0]), "+f"(c[1]), "+f"(c[2]), "+f"(c[3])
        : "r"(a0), "r"(a1), "r"(a2), "r"(a3), "r"(b0), "r"(b1));
}

__device__ __forceinline__ void cpa16(uint32_t dst, const float* src) {
    asm volatile("cp.async.cg.shared.global [%0], [%1], 16;\n" :: "r"(dst), "l"(src));
}
__device__ __forceinline__ void cpa_commit() {
    asm volatile("cp.async.commit_group;\n" ::: "memory");
}
__device__ __forceinline__ void cpa_wait0() {
    asm volatile("cp.async.wait_group 0;\n" ::: "memory");
}

// ============================================================================
// Kernel 1: k/q projections; stores tf32 hi/lo splits.
// ============================================================================
__global__ void proj_kq_kernel(const float* __restrict__ nodes,
                               const float* __restrict__ pos,
                               const float* __restrict__ rot,
                               const float* __restrict__ w_nkq,
                               const float* __restrict__ b_nkq,
                               const float* __restrict__ w_pkq,
                               const float* __restrict__ b_pkq,
                               const float* __restrict__ w_rkq)
{
    __shared__ float feat[16][144];   // 16B-aligned rows
    __shared__ float ws[64][132];
    int t = threadIdx.x;
    int row0 = blockIdx.x * 16;

    for (int idx = t; idx < 16 * 32; idx += 256) {     // float4 loads of nodes
        int r = idx >> 5, d4 = idx & 31;
        *(float4*)&feat[r][d4 * 4] = ((const float4*)(nodes + (row0 + r) * 128))[d4];
    }
    if (t < 16) {
        int r = t;
        #pragma unroll
        for (int kk = 0; kk < 3; kk++) {
            float p = pos[(row0 + r) * 3 + kk];
            float sn, cs;
            sincosf(6.28318530717958647692f * p, &sn, &cs);
            feat[r][128 + kk] = cs;
            feat[r][131 + kk] = sn;
        }
        #pragma unroll
        for (int kk = 0; kk < 4; kk++)
            feat[r][134 + kk] = rot[(row0 + r) * 4 + kk];
    }
    __syncthreads();

    int o_local = t & 63;
    int rbase   = (t >> 6) * 4;

    for (int c = 0; c < 24; c++) {
        int oglob0  = c * 64;
        int src     = oglob0 >> 9;
        int within0 = oglob0 & 511;
        const float* W; const float* B; int Din, Doff;
        if (src == 0)      { W = w_nkq; B = b_nkq; Din = 128; Doff = 0;   }
        else if (src == 1) { W = w_pkq; B = b_pkq; Din = 6;   Doff = 128; }
        else               { W = w_rkq; B = 0;     Din = 4;   Doff = 134; }

        float a0 = 0.f, a1 = 0.f, a2 = 0.f, a3 = 0.f;
        if (Din == 128) {
            for (int idx = t; idx < 64 * 32; idx += 256) {
                int oo = idx >> 5, d4 = idx & 31;
                *(float4*)&ws[oo][d4 * 4] = ((const float4*)(W + (within0 + oo) * 128))[d4];
            }
            __syncthreads();
            #pragma unroll 4
            for (int d4 = 0; d4 < 32; d4++) {
                float4 w  = *(float4*)&ws[o_local][d4 * 4];
                float4 f0 = *(float4*)&feat[rbase + 0][d4 * 4];
                float4 f1 = *(float4*)&feat[rbase + 1][d4 * 4];
                float4 f2 = *(float4*)&feat[rbase + 2][d4 * 4];
                float4 f3 = *(float4*)&feat[rbase + 3][d4 * 4];
                a0 += w.x*f0.x + w.y*f0.y + w.z*f0.z + w.w*f0.w;
                a1 += w.x*f1.x + w.y*f1.y + w.z*f1.z + w.w*f1.w;
                a2 += w.x*f2.x + w.y*f2.y + w.z*f2.z + w.w*f2.w;
                a3 += w.x*f3.x + w.y*f3.y + w.z*f3.z + w.w*f3.w;
            }
        } else {
            for (int idx = t; idx < 64 * Din; idx += 256) {
                int oo = idx / Din;
                int d  = idx - oo * Din;
                ws[oo][d] = W[(within0 + oo) * Din + d];
            }
            __syncthreads();
            for (int d = 0; d < Din; d++) {
                float w = ws[o_local][d];
                a0 += w * feat[rbase + 0][Doff + d];
                a1 += w * feat[rbase + 1][Doff + d];
                a2 += w * feat[rbase + 2][Doff + d];
                a3 += w * feat[rbase + 3][Doff + d];
            }
        }
        int within = within0 + o_local;
        if (B) { float bb = B[within]; a0 += bb; a1 += bb; a2 += bb; a3 += bb; }

        int hl = within >> 6, c64 = within & 63;
        int head = src * 8 + hl;
        float av[4] = {a0, a1, a2, a3};
        #pragma unroll
        for (int r = 0; r < 4; r++) {
            float hi = tf32r(av[r]);
            float lo = tf32r(av[r] - hi);
            int rowi = row0 + rbase + r;
            if (c64 < 32) {
                g_kh[rowi * KQSTR + head * CD + c64] = hi;
                g_kl[rowi * KQSTR + head * CD + c64] = lo;
            } else {
                g_qh[rowi * KQSTR + head * CD + (c64 - 32)] = hi;
                g_ql[rowi * KQSTR + head * CD + (c64 - 32)] = lo;
            }
        }
        __syncthreads();
    }
}

// ============================================================================
// Kernel 2: values GEMM (tf32-rounded output)
// ============================================================================
__global__ void proj_val_kernel(const float* __restrict__ nodes,
                                const float* __restrict__ w_val,
                                const float* __restrict__ b_val)
{
    __shared__ float feat[16][132];
    __shared__ float ws[64][132];
    int t = threadIdx.x;
    int row0 = blockIdx.x * 16;

    for (int idx = t; idx < 16 * 32; idx += 256) {
        int r = idx >> 5, d4 = idx & 31;
        *(float4*)&feat[r][d4 * 4] = ((const float4*)(nodes + (row0 + r) * 128))[d4];
    }
    __syncthreads();

    int o_local = t & 63;
    int rbase   = (t >> 6) * 4;

    for (int c = 0; c < 48; c++) {
        int o0 = c * 64;
        for (int idx = t; idx < 64 * 32; idx += 256) {
            int oo = idx >> 5, d4 = idx & 31;
            *(float4*)&ws[oo][d4 * 4] = ((const float4*)(w_val + (o0 + oo) * 128))[d4];
        }
        __syncthreads();

        float a0 = 0.f, a1 = 0.f, a2 = 0.f, a3 = 0.f;
        #pragma unroll 4
        for (int d4 = 0; d4 < 32; d4++) {
            float4 w  = *(float4*)&ws[o_local][d4 * 4];
            float4 f0 = *(float4*)&feat[rbase + 0][d4 * 4];
            float4 f1 = *(float4*)&feat[rbase + 1][d4 * 4];
            float4 f2 = *(float4*)&feat[rbase + 2][d4 * 4];
            float4 f3 = *(float4*)&feat[rbase + 3][d4 * 4];
            a0 += w.x*f0.x + w.y*f0.y + w.z*f0.z + w.w*f0.w;
            a1 += w.x*f1.x + w.y*f1.y + w.z*f1.z + w.w*f1.w;
            a2 += w.x*f2.x + w.y*f2.y + w.z*f2.z + w.w*f2.w;
            a3 += w.x*f3.x + w.y*f3.y + w.z*f3.z + w.w*f3.w;
        }
        int og = o0 + o_local;
        float bb = b_val[og];
        g_val[(row0 + rbase + 0) * VSTR + og] = tf32r(a0 + bb);
        g_val[(row0 + rbase + 1) * VSTR + og] = tf32r(a1 + bb);
        g_val[(row0 + rbase + 2) * VSTR + og] = tf32r(a2 + bb);
        g_val[(row0 + rbase + 3) * VSTR + og] = tf32r(a3 + bb);
        __syncthreads();
    }
}

// ============================================================================
// Kernel 3: flash attention, tf32 mma.sync, cp.async double-buffered staging.
// grid = (24, 32), block = 256 (8 warps). Per warp: 16 i-rows x 64 d-cols.
// Dynamic smem layout (floats):
//   sp   [64][36]                        @ 0      (2304)
//   sm[64] sl[64] sfac[64]               @ 2304   (192)
//   buf0: sqh[32][36] sql[32][36] sv[32][136]  @ 2496 (6656)
//   buf1: same                           @ 9152
// total 15808 floats = 63232 bytes
// ============================================================================
#define SP_OFF   0
#define ST_OFF   2304
#define BUF_OFF  2496
#define BUF_SZ   6656
#define SQH_OFF  0
#define SQL_OFF  1152
#define SV_OFF   2304
#define SVS      136
#define SMEM_BYTES 63232

extern __shared__ float smem_dyn[];

__global__ void __launch_bounds__(256, 2) flash_head_mma_kernel()
{
    float* sp    = smem_dyn + SP_OFF;      // stride 36
    float* sm_   = smem_dyn + ST_OFF;
    float* sl_   = sm_ + 64;
    float* sfac_ = sl_ + 64;

    const int t    = threadIdx.x;
    const int lane = t & 31;
    const int w    = t >> 5;
    const int gid  = lane >> 2;
    const int tig  = lane & 3;
    const int iw   = w >> 1;
    const int dblk = w & 1;

    const int h  = blockIdx.x;
    const int i0 = blockIdx.y * 64;
    const bool rot_head = (h >= 16);

    const uint32_t smem_u = (uint32_t)__cvta_generic_to_shared(smem_dyn);

    // thread's staging coordinates
    const int q_jj = t >> 3, q_c4 = t & 7;          // sq: 256 chunks

    // ---- prologue: stage tile 0 into buf0 ----
    {
        uint32_t b_u = smem_u + BUF_OFF * 4;
        cpa16(b_u + (SQH_OFF + q_jj * 36 + q_c4 * 4) * 4,
              g_qh + (size_t)q_jj * KQSTR + h * CD + q_c4 * 4);
        cpa16(b_u + (SQL_OFF + q_jj * 36 + q_c4 * 4) * 4,
              g_ql + (size_t)q_jj * KQSTR + h * CD + q_c4 * 4);
        #pragma unroll
        for (int k = 0; k < 4; k++) {
            int c = t + k * 256;
            int jj = c >> 5, d4 = c & 31;
            cpa16(b_u + (SV_OFF + jj * SVS + d4 * 4) * 4,
                  g_val + (size_t)jj * VSTR + h * ND + d4 * 4);
        }
        cpa_commit();
    }

    // ---- K fragments (hi/lo) via direct LDG, reused across all tiles ----
    uint32_t kh[4][4], kl[4][4];
    {
        int r0 = i0 + iw * 16 + gid;
        int r1 = r0 + 8;
        #pragma unroll
        for (int ks = 0; ks < 4; ks++) {
            int c0 = h * CD + ks * 8 + tig;
            int c1 = c0 + 4;
            kh[ks][0] = __float_as_uint(g_kh[r0 * KQSTR + c0]);
            kh[ks][1] = __float_as_uint(g_kh[r1 * KQSTR + c0]);
            kh[ks][2] = __float_as_uint(g_kh[r0 * KQSTR + c1]);
            kh[ks][3] = __float_as_uint(g_kh[r1 * KQSTR + c1]);
            kl[ks][0] = __float_as_uint(g_kl[r0 * KQSTR + c0]);
            kl[ks][1] = __float_as_uint(g_kl[r1 * KQSTR + c0]);
            kl[ks][2] = __float_as_uint(g_kl[r0 * KQSTR + c1]);
            kl[ks][3] = __float_as_uint(g_kl[r1 * KQSTR + c1]);
        }
    }
    if (t < 64) { sm_[t] = -1.0e30f; sl_[t] = 0.f; }

    float acc[8][4];
    #pragma unroll
    for (int nt = 0; nt < 8; nt++)
        #pragma unroll
        for (int r = 0; r < 4; r++) acc[nt][r] = 0.f;

    for (int tile = 0; tile < 64; tile++) {
        cpa_wait0();
        __syncthreads();

        // prefetch next tile into the other buffer
        if (tile + 1 < 64) {
            int j1 = (tile + 1) * 32;
            uint32_t b_u = smem_u + (BUF_OFF + ((tile + 1) & 1) * BUF_SZ) * 4;
            cpa16(b_u + (SQH_OFF + q_jj * 36 + q_c4 * 4) * 4,
                  g_qh + (size_t)(j1 + q_jj) * KQSTR + h * CD + q_c4 * 4);
            cpa16(b_u + (SQL_OFF + q_jj * 36 + q_c4 * 4) * 4,
                  g_ql + (size_t)(j1 + q_jj) * KQSTR + h * CD + q_c4 * 4);
            #pragma unroll
            for (int k = 0; k < 4; k++) {
                int c = t + k * 256;
                int jj = c >> 5, d4 = c & 31;
                cpa16(b_u + (SV_OFF + jj * SVS + d4 * 4) * 4,
                      g_val + (size_t)(j1 + jj) * VSTR + h * ND + d4 * 4);
            }
            cpa_commit();
        }

        float* B   = smem_dyn + BUF_OFF + (tile & 1) * BUF_SZ;
        float* sqh = B + SQH_OFF;
        float* sql = B + SQL_OFF;
        float* sv  = B + SV_OFF;

        // ---- MMA1 (3xTF32): S[64 x 32] = K @ Q^T ----
        #pragma unroll
        for (int s = 0; s < 2; s++) {
            int jb = dblk * 2 + s;
            float d[4] = {0.f, 0.f, 0.f, 0.f};
            #pragma unroll
            for (int ks = 0; ks < 4; ks++) {
                const float* qhp = sqh + (jb * 8 + gid) * 36 + ks * 8 + tig;
                const float* qlp = sql + (jb * 8 + gid) * 36 + ks * 8 + tig;
                uint32_t b0h = __float_as_uint(qhp[0]);
                uint32_t b1h = __float_as_uint(qhp[4]);
                uint32_t b0l = __float_as_uint(qlp[0]);
                uint32_t b1l = __float_as_uint(qlp[4]);
                mma_tf32(d, kh[ks][0], kh[ks][1], kh[ks][2], kh[ks][3], b0h, b1h);
                mma_tf32(d, kh[ks][0], kh[ks][1], kh[ks][2], kh[ks][3], b0l, b1l);
                mma_tf32(d, kl[ks][0], kl[ks][1], kl[ks][2], kl[ks][3], b0h, b1h);
            }
            int ro = (iw * 16 + gid) * 36 + jb * 8 + 2 * tig;
            *(float2*)&sp[ro]           = make_float2(d[0], d[1]);
            *(float2*)&sp[ro + 8 * 36]  = make_float2(d[2], d[3]);
        }
        __syncthreads();

        // ---- online softmax: thread t -> row t>>2, 8 cols ----
        {
            int row = t >> 2;
            int c0  = (t & 3) * 8;
            float4 e0 = *(float4*)&sp[row * 36 + c0];
            float4 e1 = *(float4*)&sp[row * 36 + c0 + 4];
            if (rot_head) {
                e0.x *= e0.x; e0.y *= e0.y; e0.z *= e0.z; e0.w *= e0.w;
                e1.x *= e1.x; e1.y *= e1.y; e1.z *= e1.z; e1.w *= e1.w;
            }
            float mx8 = fmaxf(fmaxf(fmaxf(e0.x, e0.y), fmaxf(e0.z, e0.w)),
                              fmaxf(fmaxf(e1.x, e1.y), fmaxf(e1.z, e1.w)));
            mx8 = fmaxf(mx8, __shfl_xor_sync(0xffffffffu, mx8, 1));
            mx8 = fmaxf(mx8, __shfl_xor_sync(0xffffffffu, mx8, 2));
            float mo = sm_[row];
            float mx = fmaxf(mo, mx8);
            float p0 = __expf(e0.x - mx), p1 = __expf(e0.y - mx);
            float p2 = __expf(e0.z - mx), p3 = __expf(e0.w - mx);
            float p4 = __expf(e1.x - mx), p5 = __expf(e1.y - mx);
            float p6 = __expf(e1.z - mx), p7 = __expf(e1.w - mx);
            float sum = ((p0 + p1) + (p2 + p3)) + ((p4 + p5) + (p6 + p7));
            float4 w0 = make_float4(tf32r(p0), tf32r(p1), tf32r(p2), tf32r(p3));
            float4 w1 = make_float4(tf32r(p4), tf32r(p5), tf32r(p6), tf32r(p7));
            *(float4*)&sp[row * 36 + c0]     = w0;
            *(float4*)&sp[row * 36 + c0 + 4] = w1;
            sum += __shfl_xor_sync(0xffffffffu, sum, 1);
            sum += __shfl_xor_sync(0xffffffffu, sum, 2);
            if ((t & 3) == 0) {
                float fac = __expf(mo - mx);
                sl_[row]   = sl_[row] * fac + sum;
                sm_[row]   = mx;
                sfac_[row] = fac;
            }
        }
        __syncthreads();

        // ---- rescale accumulators ----
        {
            float f0 = sfac_[iw * 16 + gid];
            float f1 = sfac_[iw * 16 + gid + 8];
            #pragma unroll
            for (int nt = 0; nt < 8; nt++) {
                acc[nt][0] *= f0; acc[nt][1] *= f0;
                acc[nt][2] *= f1; acc[nt][3] *= f1;
            }
        }

        // ---- MMA2 (1xTF32): out[16 x 64] += P[16 x 32] @ V[32 x 64] ----
        #pragma unroll
        for (int ks = 0; ks < 4; ks++) {
            const float* pp = sp + (iw * 16 + gid) * 36 + ks * 8 + tig;
            uint32_t a0 = __float_as_uint(pp[0]);
            uint32_t a1 = __float_as_uint(pp[8 * 36]);
            uint32_t a2 = __float_as_uint(pp[4]);
            uint32_t a3 = __float_as_uint(pp[8 * 36 + 4]);
            const float* v0 = sv + (ks * 8 + tig) * SVS + dblk * 64 + gid;
            const float* v1 = v0 + 4 * SVS;
            #pragma unroll
            for (int nt = 0; nt < 8; nt++) {
                uint32_t b0 = __float_as_uint(v0[nt * 8]);
                uint32_t b1 = __float_as_uint(v1[nt * 8]);
                mma_tf32(acc[nt], a0, a1, a2, a3, b0, b1);
            }
        }
        // no barrier: top-of-loop wait+sync covers buffer reuse hazards
    }

    // ---- epilogue: normalize, write per-head partial ----
    {
        int r0 = iw * 16 + gid;
        int r1 = r0 + 8;
        float rl0 = 1.f / sl_[r0];
        float rl1 = 1.f / sl_[r1];
        #pragma unroll
        for (int nt = 0; nt < 8; nt++) {
            int col = dblk * 64 + nt * 8 + 2 * tig;
            float2 v0 = make_float2(acc[nt][0] * rl0, acc[nt][1] * rl0);
            float2 v1 = make_float2(acc[nt][2] * rl1, acc[nt][3] * rl1);
            *(float2*)&g_part[((size_t)h * SEQ + i0 + r0) * ND + col] = v0;
            *(float2*)&g_part[((size_t)h * SEQ + i0 + r1) * ND + col] = v1;
        }
    }
}

// ============================================================================
// Kernel 4: sum 24 head partials -> out [2048, 128]
// ============================================================================
__global__ void reduce_kernel(float* __restrict__ out)
{
    int idx = blockIdx.x * 256 + threadIdx.x;
    float s = 0.f;
    #pragma unroll
    for (int h = 0; h < NH; h++)
        s += g_part[(size_t)h * (SEQ * ND) + idx];
    out[idx] = s;
}

// ============================================================================
extern "C" void kernel_launch(void* const* d_in, const int* in_sizes, int n_in,
                              void* d_out, int out_size)
{
    const float* nodes = (const float*)d_in[0];
    const float* pos   = (const float*)d_in[1];
    const float* rot   = (const float*)d_in[2];
    const float* w_nkq = (const float*)d_in[3];
    const float* b_nkq = (const float*)d_in[4];
    const float* w_pkq = (const float*)d_in[5];
    const float* b_pkq = (const float*)d_in[6];
    const float* w_rkq = (const float*)d_in[7];
    const float* w_val = (const float*)d_in[8];
    const float* b_val = (const float*)d_in[9];
    float* out = (float*)d_out;

    cudaFuncSetAttribute(flash_head_mma_kernel,
                         cudaFuncAttributeMaxDynamicSharedMemorySize, SMEM_BYTES);

    proj_kq_kernel<<<SEQ / 16, 256>>>(nodes, pos, rot, w_nkq, b_nkq,
                                      w_pkq, b_pkq, w_rkq);
    proj_val_kernel<<<SEQ / 16, 256>>>(nodes, w_val, b_val);
    dim3 g3(NH, SEQ / 64);
    flash_head_mma_kernel<<<g3, 256, SMEM_BYTES>>>();
    reduce_kernel<<<(SEQ * ND) / 256, 256>>>(out);
}

// round 7
// speedup vs baseline: 3.0806x; 1.0029x over previous
#include <cuda_runtime.h>
#include <math.h>
#include <stdint.h>

// Problem constants
#define SEQ   2048
#define ND    128      // node_dim
#define NH    24       // 3*H total heads
#define CD    32       // channels per head (k/q)
#define KQSTR (NH*CD)  // 768
#define VSTR  (NH*ND)  // 3072

// ---------------- scratch (device globals) ----------------
__device__ float g_kh  [SEQ * NH * CD];
__device__ float g_kl  [SEQ * NH * CD];
__device__ float g_qh  [SEQ * NH * CD];
__device__ float g_ql  [SEQ * NH * CD];
__device__ float g_val [SEQ * NH * ND];     // tf32-rounded at store
__device__ float g_part[NH  * SEQ * ND];

// ---------------- helpers ----------------
__device__ __forceinline__ float tf32r(float x) {
    uint32_t u;
    asm("cvt.rna.tf32.f32 %0, %1;" : "=r"(u) : "f"(x));
    return __uint_as_float(u);
}

__device__ __forceinline__ void mma_tf32(float c[4],
                                         uint32_t a0, uint32_t a1, uint32_t a2, uint32_t a3,
                                         uint32_t b0, uint32_t b1) {
    asm volatile(
        "mma.sync.aligned.m16n8k8.row.col.f32.tf32.tf32.f32 "
        "{%0,%1,%2,%3}, {%4,%5,%6,%7}, {%8,%9}, {%0,%1,%2,%3};"
        : "+f"(c[0]), "+f"(c[1]), "+f"(c[2]), "+f"(c[3])
        : "r"(a0), "r"(a1), "r"(a2), "r"(a3), "r"(b0), "r"(b1));
}

__device__ __forceinline__ void cpa16(uint32_t dst, const float* src) {
    asm volatile("cp.async.cg.shared.global [%0], [%1], 16;\n" :: "r"(dst), "l"(src));
}
__device__ __forceinline__ void cpa_commit() {
    asm volatile("cp.async.commit_group;\n" ::: "memory");
}
__device__ __forceinline__ void cpa_wait0() {
    asm volatile("cp.async.wait_group 0;\n" ::: "memory");
}

// ============================================================================
// Kernel 1: k/q projections; stores tf32 hi/lo splits.
// ============================================================================
__global__ void proj_kq_kernel(const float* __restrict__ nodes,
                               const float* __restrict__ pos,
                               const float* __restrict__ rot,
                               const float* __restrict__ w_nkq,
                               const float* __restrict__ b_nkq,
                               const float* __restrict__ w_pkq,
                               const float* __restrict__ b_pkq,
                               const float* __restrict__ w_rkq)
{
    __shared__ float feat[16][144];   // 16B-aligned rows
    __shared__ float ws[64][132];
    int t = threadIdx.x;
    int row0 = blockIdx.x * 16;

    for (int idx = t; idx < 16 * 32; idx += 256) {     // float4 loads of nodes
        int r = idx >> 5, d4 = idx & 31;
        *(float4*)&feat[r][d4 * 4] = ((const float4*)(nodes + (row0 + r) * 128))[d4];
    }
    if (t < 16) {
        int r = t;
        #pragma unroll
        for (int kk = 0; kk < 3; kk++) {
            float p = pos[(row0 + r) * 3 + kk];
            float sn, cs;
            sincosf(6.28318530717958647692f * p, &sn, &cs);
            feat[r][128 + kk] = cs;
            feat[r][131 + kk] = sn;
        }
        #pragma unroll
        for (int kk = 0; kk < 4; kk++)
            feat[r][134 + kk] = rot[(row0 + r) * 4 + kk];
    }
    __syncthreads();

    int o_local = t & 63;
    int rbase   = (t >> 6) * 4;

    for (int c = 0; c < 24; c++) {
        int oglob0  = c * 64;
        int src     = oglob0 >> 9;
        int within0 = oglob0 & 511;
        const float* W; const float* B; int Din, Doff;
        if (src == 0)      { W = w_nkq; B = b_nkq; Din = 128; Doff = 0;   }
        else if (src == 1) { W = w_pkq; B = b_pkq; Din = 6;   Doff = 128; }
        else               { W = w_rkq; B = 0;     Din = 4;   Doff = 134; }

        float a0 = 0.f, a1 = 0.f, a2 = 0.f, a3 = 0.f;
        if (Din == 128) {
            for (int idx = t; idx < 64 * 32; idx += 256) {
                int oo = idx >> 5, d4 = idx & 31;
                *(float4*)&ws[oo][d4 * 4] = ((const float4*)(W + (within0 + oo) * 128))[d4];
            }
            __syncthreads();
            #pragma unroll 4
            for (int d4 = 0; d4 < 32; d4++) {
                float4 w  = *(float4*)&ws[o_local][d4 * 4];
                float4 f0 = *(float4*)&feat[rbase + 0][d4 * 4];
                float4 f1 = *(float4*)&feat[rbase + 1][d4 * 4];
                float4 f2 = *(float4*)&feat[rbase + 2][d4 * 4];
                float4 f3 = *(float4*)&feat[rbase + 3][d4 * 4];
                a0 += w.x*f0.x + w.y*f0.y + w.z*f0.z + w.w*f0.w;
                a1 += w.x*f1.x + w.y*f1.y + w.z*f1.z + w.w*f1.w;
                a2 += w.x*f2.x + w.y*f2.y + w.z*f2.z + w.w*f2.w;
                a3 += w.x*f3.x + w.y*f3.y + w.z*f3.z + w.w*f3.w;
            }
        } else {
            for (int idx = t; idx < 64 * Din; idx += 256) {
                int oo = idx / Din;
                int d  = idx - oo * Din;
                ws[oo][d] = W[(within0 + oo) * Din + d];
            }
            __syncthreads();
            for (int d = 0; d < Din; d++) {
                float w = ws[o_local][d];
                a0 += w * feat[rbase + 0][Doff + d];
                a1 += w * feat[rbase + 1][Doff + d];
                a2 += w * feat[rbase + 2][Doff + d];
                a3 += w * feat[rbase + 3][Doff + d];
            }
        }
        int within = within0 + o_local;
        if (B) { float bb = B[within]; a0 += bb; a1 += bb; a2 += bb; a3 += bb; }

        int hl = within >> 6, c64 = within & 63;
        int head = src * 8 + hl;
        float av[4] = {a0, a1, a2, a3};
        #pragma unroll
        for (int r = 0; r < 4; r++) {
            float hi = tf32r(av[r]);
            float lo = tf32r(av[r] - hi);
            int rowi = row0 + rbase + r;
            if (c64 < 32) {
                g_kh[rowi * KQSTR + head * CD + c64] = hi;
                g_kl[rowi * KQSTR + head * CD + c64] = lo;
            } else {
                g_qh[rowi * KQSTR + head * CD + (c64 - 32)] = hi;
                g_ql[rowi * KQSTR + head * CD + (c64 - 32)] = lo;
            }
        }
        __syncthreads();
    }
}

// ============================================================================
// Kernel 2: values GEMM (tf32-rounded output)
// ============================================================================
__global__ void proj_val_kernel(const float* __restrict__ nodes,
                                const float* __restrict__ w_val,
                                const float* __restrict__ b_val)
{
    __shared__ float feat[16][132];
    __shared__ float ws[64][132];
    int t = threadIdx.x;
    int row0 = blockIdx.x * 16;

    for (int idx = t; idx < 16 * 32; idx += 256) {
        int r = idx >> 5, d4 = idx & 31;
        *(float4*)&feat[r][d4 * 4] = ((const float4*)(nodes + (row0 + r) * 128))[d4];
    }
    __syncthreads();

    int o_local = t & 63;
    int rbase   = (t >> 6) * 4;

    for (int c = 0; c < 48; c++) {
        int o0 = c * 64;
        for (int idx = t; idx < 64 * 32; idx += 256) {
            int oo = idx >> 5, d4 = idx & 31;
            *(float4*)&ws[oo][d4 * 4] = ((const float4*)(w_val + (o0 + oo) * 128))[d4];
        }
        __syncthreads();

        float a0 = 0.f, a1 = 0.f, a2 = 0.f, a3 = 0.f;
        #pragma unroll 4
        for (int d4 = 0; d4 < 32; d4++) {
            float4 w  = *(float4*)&ws[o_local][d4 * 4];
            float4 f0 = *(float4*)&feat[rbase + 0][d4 * 4];
            float4 f1 = *(float4*)&feat[rbase + 1][d4 * 4];
            float4 f2 = *(float4*)&feat[rbase + 2][d4 * 4];
            float4 f3 = *(float4*)&feat[rbase + 3][d4 * 4];
            a0 += w.x*f0.x + w.y*f0.y + w.z*f0.z + w.w*f0.w;
            a1 += w.x*f1.x + w.y*f1.y + w.z*f1.z + w.w*f1.w;
            a2 += w.x*f2.x + w.y*f2.y + w.z*f2.z + w.w*f2.w;
            a3 += w.x*f3.x + w.y*f3.y + w.z*f3.z + w.w*f3.w;
        }
        int og = o0 + o_local;
        float bb = b_val[og];
        g_val[(row0 + rbase + 0) * VSTR + og] = tf32r(a0 + bb);
        g_val[(row0 + rbase + 1) * VSTR + og] = tf32r(a1 + bb);
        g_val[(row0 + rbase + 2) * VSTR + og] = tf32r(a2 + bb);
        g_val[(row0 + rbase + 3) * VSTR + og] = tf32r(a3 + bb);
        __syncthreads();
    }
}

// ============================================================================
// Kernel 3: flash attention, tf32 mma.sync, cp.async double-buffered staging.
// grid = (24, 32), block = 256 (8 warps). Per warp: 16 i-rows x 64 d-cols.
// Dynamic smem layout (floats):
//   sp   [64][36]                        @ 0      (2304)
//   sm[64] sl[64] sfac[64]               @ 2304   (192)
//   buf0: sqh[32][36] sql[32][36] sv[32][136]  @ 2496 (6656)
//   buf1: same                           @ 9152
// total 15808 floats = 63232 bytes
// ============================================================================
#define SP_OFF   0
#define ST_OFF   2304
#define BUF_OFF  2496
#define BUF_SZ   6656
#define SQH_OFF  0
#define SQL_OFF  1152
#define SV_OFF   2304
#define SVS      136
#define SMEM_BYTES 63232

extern __shared__ float smem_dyn[];

__global__ void __launch_bounds__(256, 2) flash_head_mma_kernel()
{
    float* sp    = smem_dyn + SP_OFF;      // stride 36
    float* sm_   = smem_dyn + ST_OFF;
    float* sl_   = sm_ + 64;
    float* sfac_ = sl_ + 64;

    const int t    = threadIdx.x;
    const int lane = t & 31;
    const int w    = t >> 5;
    const int gid  = lane >> 2;
    const int tig  = lane & 3;
    const int iw   = w >> 1;
    const int dblk = w & 1;

    const int h  = blockIdx.x;
    const int i0 = blockIdx.y * 64;
    const bool rot_head = (h >= 16);

    const uint32_t smem_u = (uint32_t)__cvta_generic_to_shared(smem_dyn);

    // thread's staging coordinates
    const int q_jj = t >> 3, q_c4 = t & 7;          // sq: 256 chunks

    // ---- prologue: stage tile 0 into buf0 ----
    {
        uint32_t b_u = smem_u + BUF_OFF * 4;
        cpa16(b_u + (SQH_OFF + q_jj * 36 + q_c4 * 4) * 4,
              g_qh + (size_t)q_jj * KQSTR + h * CD + q_c4 * 4);
        cpa16(b_u + (SQL_OFF + q_jj * 36 + q_c4 * 4) * 4,
              g_ql + (size_t)q_jj * KQSTR + h * CD + q_c4 * 4);
        #pragma unroll
        for (int k = 0; k < 4; k++) {
            int c = t + k * 256;
            int jj = c >> 5, d4 = c & 31;
            cpa16(b_u + (SV_OFF + jj * SVS + d4 * 4) * 4,
                  g_val + (size_t)jj * VSTR + h * ND + d4 * 4);
        }
        cpa_commit();
    }

    // ---- K fragments (hi/lo) via direct LDG, reused across all tiles ----
    uint32_t kh[4][4], kl[4][4];
    {
        int r0 = i0 + iw * 16 + gid;
        int r1 = r0 + 8;
        #pragma unroll
        for (int ks = 0; ks < 4; ks++) {
            int c0 = h * CD + ks * 8 + tig;
            int c1 = c0 + 4;
            kh[ks][0] = __float_as_uint(g_kh[r0 * KQSTR + c0]);
            kh[ks][1] = __float_as_uint(g_kh[r1 * KQSTR + c0]);
            kh[ks][2] = __float_as_uint(g_kh[r0 * KQSTR + c1]);
            kh[ks][3] = __float_as_uint(g_kh[r1 * KQSTR + c1]);
            kl[ks][0] = __float_as_uint(g_kl[r0 * KQSTR + c0]);
            kl[ks][1] = __float_as_uint(g_kl[r1 * KQSTR + c0]);
            kl[ks][2] = __float_as_uint(g_kl[r0 * KQSTR + c1]);
            kl[ks][3] = __float_as_uint(g_kl[r1 * KQSTR + c1]);
        }
    }
    if (t < 64) { sm_[t] = -1.0e30f; sl_[t] = 0.f; }

    float acc[8][4];
    #pragma unroll
    for (int nt = 0; nt < 8; nt++)
        #pragma unroll
        for (int r = 0; r < 4; r++) acc[nt][r] = 0.f;

    for (int tile = 0; tile < 64; tile++) {
        cpa_wait0();
        __syncthreads();

        // prefetch next tile into the other buffer
        if (tile + 1 < 64) {
            int j1 = (tile + 1) * 32;
            uint32_t b_u = smem_u + (BUF_OFF + ((tile + 1) & 1) * BUF_SZ) * 4;
            cpa16(b_u + (SQH_OFF + q_jj * 36 + q_c4 * 4) * 4,
                  g_qh + (size_t)(j1 + q_jj) * KQSTR + h * CD + q_c4 * 4);
            cpa16(b_u + (SQL_OFF + q_jj * 36 + q_c4 * 4) * 4,
                  g_ql + (size_t)(j1 + q_jj) * KQSTR + h * CD + q_c4 * 4);
            #pragma unroll
            for (int k = 0; k < 4; k++) {
                int c = t + k * 256;
                int jj = c >> 5, d4 = c & 31;
                cpa16(b_u + (SV_OFF + jj * SVS + d4 * 4) * 4,
                      g_val + (size_t)(j1 + jj) * VSTR + h * ND + d4 * 4);
            }
            cpa_commit();
        }

        float* B   = smem_dyn + BUF_OFF + (tile & 1) * BUF_SZ;
        float* sqh = B + SQH_OFF;
        float* sql = B + SQL_OFF;
        float* sv  = B + SV_OFF;

        // ---- MMA1 (3xTF32): S[64 x 32] = K @ Q^T ----
        #pragma unroll
        for (int s = 0; s < 2; s++) {
            int jb = dblk * 2 + s;
            float d[4] = {0.f, 0.f, 0.f, 0.f};
            #pragma unroll
            for (int ks = 0; ks < 4; ks++) {
                const float* qhp = sqh + (jb * 8 + gid) * 36 + ks * 8 + tig;
                const float* qlp = sql + (jb * 8 + gid) * 36 + ks * 8 + tig;
                uint32_t b0h = __float_as_uint(qhp[0]);
                uint32_t b1h = __float_as_uint(qhp[4]);
                uint32_t b0l = __float_as_uint(qlp[0]);
                uint32_t b1l = __float_as_uint(qlp[4]);
                mma_tf32(d, kh[ks][0], kh[ks][1], kh[ks][2], kh[ks][3], b0h, b1h);
                mma_tf32(d, kh[ks][0], kh[ks][1], kh[ks][2], kh[ks][3], b0l, b1l);
                mma_tf32(d, kl[ks][0], kl[ks][1], kl[ks][2], kl[ks][3], b0h, b1h);
            }
            int ro = (iw * 16 + gid) * 36 + jb * 8 + 2 * tig;
            *(float2*)&sp[ro]           = make_float2(d[0], d[1]);
            *(float2*)&sp[ro + 8 * 36]  = make_float2(d[2], d[3]);
        }
        __syncthreads();

        // ---- online softmax: thread t -> row t>>2, 8 cols ----
        {
            int row = t >> 2;
            int c0  = (t & 3) * 8;
            float4 e0 = *(float4*)&sp[row * 36 + c0];
            float4 e1 = *(float4*)&sp[row * 36 + c0 + 4];
            if (rot_head) {
                e0.x *= e0.x; e0.y *= e0.y; e0.z *= e0.z; e0.w *= e0.w;
                e1.x *= e1.x; e1.y *= e1.y; e1.z *= e1.z; e1.w *= e1.w;
            }
            float mx8 = fmaxf(fmaxf(fmaxf(e0.x, e0.y), fmaxf(e0.z, e0.w)),
                              fmaxf(fmaxf(e1.x, e1.y), fmaxf(e1.z, e1.w)));
            mx8 = fmaxf(mx8, __shfl_xor_sync(0xffffffffu, mx8, 1));
            mx8 = fmaxf(mx8, __shfl_xor_sync(0xffffffffu, mx8, 2));
            float mo = sm_[row];
            float mx = fmaxf(mo, mx8);
            float p0 = __expf(e0.x - mx), p1 = __expf(e0.y - mx);
            float p2 = __expf(e0.z - mx), p3 = __expf(e0.w - mx);
            float p4 = __expf(e1.x - mx), p5 = __expf(e1.y - mx);
            float p6 = __expf(e1.z - mx), p7 = __expf(e1.w - mx);
            float sum = ((p0 + p1) + (p2 + p3)) + ((p4 + p5) + (p6 + p7));
            float4 w0 = make_float4(tf32r(p0), tf32r(p1), tf32r(p2), tf32r(p3));
            float4 w1 = make_float4(tf32r(p4), tf32r(p5), tf32r(p6), tf32r(p7));
            *(float4*)&sp[row * 36 + c0]     = w0;
            *(float4*)&sp[row * 36 + c0 + 4] = w1;
            sum += __shfl_xor_sync(0xffffffffu, sum, 1);
            sum += __shfl_xor_sync(0xffffffffu, sum, 2);
            if ((t & 3) == 0) {
                float fac = __expf(mo - mx);
                sl_[row]   = sl_[row] * fac + sum;
                sm_[row]   = mx;
                sfac_[row] = fac;
            }
        }
        __syncthreads();

        // ---- rescale accumulators ----
        {
            float f0 = sfac_[iw * 16 + gid];
            float f1 = sfac_[iw * 16 + gid + 8];
            #pragma unroll
            for (int nt = 0; nt < 8; nt++) {
                acc[nt][0] *= f0; acc[nt][1] *= f0;
                acc[nt][2] *= f1; acc[nt][3] *= f1;
            }
        }

        // ---- MMA2 (1xTF32): out[16 x 64] += P[16 x 32] @ V[32 x 64] ----
        #pragma unroll
        for (int ks = 0; ks < 4; ks++) {
            const float* pp = sp + (iw * 16 + gid) * 36 + ks * 8 + tig;
            uint32_t a0 = __float_as_uint(pp[0]);
            uint32_t a1 = __float_as_uint(pp[8 * 36]);
            uint32_t a2 = __float_as_uint(pp[4]);
            uint32_t a3 = __float_as_uint(pp[8 * 36 + 4]);
            const float* v0 = sv + (ks * 8 + tig) * SVS + dblk * 64 + gid;
            const float* v1 = v0 + 4 * SVS;
            #pragma unroll
            for (int nt = 0; nt < 8; nt++) {
                uint32_t b0 = __float_as_uint(v0[nt * 8]);
                uint32_t b1 = __float_as_uint(v1[nt * 8]);
                mma_tf32(acc[nt], a0, a1, a2, a3, b0, b1);
            }
        }
        // no barrier: top-of-loop wait+sync covers buffer reuse hazards
    }

    // ---- epilogue: normalize, write per-head partial ----
    {
        int r0 = iw * 16 + gid;
        int r1 = r0 + 8;
        float rl0 = 1.f / sl_[r0];
        float rl1 = 1.f / sl_[r1];
        #pragma unroll
        for (int nt = 0; nt < 8; nt++) {
            int col = dblk * 64 + nt * 8 + 2 * tig;
            float2 v0 = make_float2(acc[nt][0] * rl0, acc[nt][1] * rl0);
            float2 v1 = make_float2(acc[nt][2] * rl1, acc[nt][3] * rl1);
            *(float2*)&g_part[((size_t)h * SEQ + i0 + r0) * ND + col] = v0;
            *(float2*)&g_part[((size_t)h * SEQ + i0 + r1) * ND + col] = v1;
        }
    }
}

// ============================================================================
// Kernel 4: sum 24 head partials -> out [2048, 128]
// ============================================================================
__global__ void reduce_kernel(float* __restrict__ out)
{
    int idx = blockIdx.x * 256 + threadIdx.x;
    float s = 0.f;
    #pragma unroll
    for (int h = 0; h < NH; h++)
        s += g_part[(size_t)h * (SEQ * ND) + idx];
    out[idx] = s;
}

// ============================================================================
extern "C" void kernel_launch(void* const* d_in, const int* in_sizes, int n_in,
                              void* d_out, int out_size)
{
    const float* nodes = (const float*)d_in[0];
    const float* pos   = (const float*)d_in[1];
    const float* rot   = (const float*)d_in[2];
    const float* w_nkq = (const float*)d_in[3];
    const float* b_nkq = (const float*)d_in[4];
    const float* w_pkq = (const float*)d_in[5];
    const float* b_pkq = (const float*)d_in[6];
    const float* w_rkq = (const float*)d_in[7];
    const float* w_val = (const float*)d_in[8];
    const float* b_val = (const float*)d_in[9];
    float* out = (float*)d_out;

    cudaFuncSetAttribute(flash_head_mma_kernel,
                         cudaFuncAttributeMaxDynamicSharedMemorySize, SMEM_BYTES);

    proj_kq_kernel<<<SEQ / 16, 256>>>(nodes, pos, rot, w_nkq, b_nkq,
                                      w_pkq, b_pkq, w_rkq);
    proj_val_kernel<<<SEQ / 16, 256>>>(nodes, w_val, b_val);
    dim3 g3(NH, SEQ / 64);
    flash_head_mma_kernel<<<g3, 256, SMEM_BYTES>>>();
    reduce_kernel<<<(SEQ * ND) / 256, 256>>>(out);
}

// round 8
// speedup vs baseline: 4.5460x; 1.4757x over previous
#include <cuda_runtime.h>
#include <cuda_fp16.h>
#include <math.h>
#include <stdint.h>

// Problem constants
#define SEQ   2048
#define ND    128      // node_dim
#define NH    24       // 3*H total heads
#define CD    32       // channels per head (k/q)
#define KQSTR (NH*CD)  // 768
#define VSTR  (NH*ND)  // 3072

// ---------------- scratch (device globals) ----------------
__device__ __half  g_kh16 [SEQ * NH * CD];   // fp16 hi of k
__device__ __half  g_kl16 [SEQ * NH * CD];   // fp16 lo of k
__device__ __half  g_qh16 [SEQ * NH * CD];
__device__ __half  g_ql16 [SEQ * NH * CD];
__device__ __half2 g_valp [(SEQ/2) * NH * ND];  // half2(v[2j], v[2j+1]) per (jpair,h,d)
__device__ float   g_part [NH * SEQ * ND];

// ---------------- helpers ----------------
__device__ __forceinline__ void mma_f16(float c[4],
                                        uint32_t a0, uint32_t a1, uint32_t a2, uint32_t a3,
                                        uint32_t b0, uint32_t b1) {
    asm volatile(
        "mma.sync.aligned.m16n8k16.row.col.f32.f16.f16.f32 "
        "{%0,%1,%2,%3}, {%4,%5,%6,%7}, {%8,%9}, {%0,%1,%2,%3};"
        : "+f"(c[0]), "+f"(c[1]), "+f"(c[2]), "+f"(c[3])
        : "r"(a0), "r"(a1), "r"(a2), "r"(a3), "r"(b0), "r"(b1));
}

__device__ __forceinline__ void cpa16(uint32_t dst, const void* src) {
    asm volatile("cp.async.cg.shared.global [%0], [%1], 16;\n" :: "r"(dst), "l"(src));
}
__device__ __forceinline__ void cpa_commit() {
    asm volatile("cp.async.commit_group;\n" ::: "memory");
}
__device__ __forceinline__ void cpa_wait0() {
    asm volatile("cp.async.wait_group 0;\n" ::: "memory");
}

// ============================================================================
// Kernel 1: k/q projections; stores fp16 hi/lo splits.
// ============================================================================
__global__ void proj_kq_kernel(const float* __restrict__ nodes,
                               const float* __restrict__ pos,
                               const float* __restrict__ rot,
                               const float* __restrict__ w_nkq,
                               const float* __restrict__ b_nkq,
                               const float* __restrict__ w_pkq,
                               const float* __restrict__ b_pkq,
                               const float* __restrict__ w_rkq)
{
    __shared__ float feat[16][144];
    __shared__ float ws[64][132];
    int t = threadIdx.x;
    int row0 = blockIdx.x * 16;

    for (int idx = t; idx < 16 * 32; idx += 256) {
        int r = idx >> 5, d4 = idx & 31;
        *(float4*)&feat[r][d4 * 4] = ((const float4*)(nodes + (row0 + r) * 128))[d4];
    }
    if (t < 16) {
        int r = t;
        #pragma unroll
        for (int kk = 0; kk < 3; kk++) {
            float p = pos[(row0 + r) * 3 + kk];
            float sn, cs;
            sincosf(6.28318530717958647692f * p, &sn, &cs);
            feat[r][128 + kk] = cs;
            feat[r][131 + kk] = sn;
        }
        #pragma unroll
        for (int kk = 0; kk < 4; kk++)
            feat[r][134 + kk] = rot[(row0 + r) * 4 + kk];
    }
    __syncthreads();

    int o_local = t & 63;
    int rbase   = (t >> 6) * 4;

    for (int c = 0; c < 24; c++) {
        int oglob0  = c * 64;
        int src     = oglob0 >> 9;
        int within0 = oglob0 & 511;
        const float* W; const float* B; int Din, Doff;
        if (src == 0)      { W = w_nkq; B = b_nkq; Din = 128; Doff = 0;   }
        else if (src == 1) { W = w_pkq; B = b_pkq; Din = 6;   Doff = 128; }
        else               { W = w_rkq; B = 0;     Din = 4;   Doff = 134; }

        float a0 = 0.f, a1 = 0.f, a2 = 0.f, a3 = 0.f;
        if (Din == 128) {
            for (int idx = t; idx < 64 * 32; idx += 256) {
                int oo = idx >> 5, d4 = idx & 31;
                *(float4*)&ws[oo][d4 * 4] = ((const float4*)(W + (within0 + oo) * 128))[d4];
            }
            __syncthreads();
            #pragma unroll 4
            for (int d4 = 0; d4 < 32; d4++) {
                float4 w  = *(float4*)&ws[o_local][d4 * 4];
                float4 f0 = *(float4*)&feat[rbase + 0][d4 * 4];
                float4 f1 = *(float4*)&feat[rbase + 1][d4 * 4];
                float4 f2 = *(float4*)&feat[rbase + 2][d4 * 4];
                float4 f3 = *(float4*)&feat[rbase + 3][d4 * 4];
                a0 += w.x*f0.x + w.y*f0.y + w.z*f0.z + w.w*f0.w;
                a1 += w.x*f1.x + w.y*f1.y + w.z*f1.z + w.w*f1.w;
                a2 += w.x*f2.x + w.y*f2.y + w.z*f2.z + w.w*f2.w;
                a3 += w.x*f3.x + w.y*f3.y + w.z*f3.z + w.w*f3.w;
            }
        } else {
            for (int idx = t; idx < 64 * Din; idx += 256) {
                int oo = idx / Din;
                int d  = idx - oo * Din;
                ws[oo][d] = W[(within0 + oo) * Din + d];
            }
            __syncthreads();
            for (int d = 0; d < Din; d++) {
                float w = ws[o_local][d];
                a0 += w * feat[rbase + 0][Doff + d];
                a1 += w * feat[rbase + 1][Doff + d];
                a2 += w * feat[rbase + 2][Doff + d];
                a3 += w * feat[rbase + 3][Doff + d];
            }
        }
        int within = within0 + o_local;
        if (B) { float bb = B[within]; a0 += bb; a1 += bb; a2 += bb; a3 += bb; }

        int hl = within >> 6, c64 = within & 63;
        int head = src * 8 + hl;
        float av[4] = {a0, a1, a2, a3};
        #pragma unroll
        for (int r = 0; r < 4; r++) {
            __half hi = __float2half_rn(av[r]);
            __half lo = __float2half_rn(av[r] - __half2float(hi));
            int rowi = row0 + rbase + r;
            if (c64 < 32) {
                g_kh16[rowi * KQSTR + head * CD + c64] = hi;
                g_kl16[rowi * KQSTR + head * CD + c64] = lo;
            } else {
                g_qh16[rowi * KQSTR + head * CD + (c64 - 32)] = hi;
                g_ql16[rowi * KQSTR + head * CD + (c64 - 32)] = lo;
            }
        }
        __syncthreads();
    }
}

// ============================================================================
// Kernel 2: values GEMM; output packed as half2 over consecutive j pairs.
// ============================================================================
__global__ void proj_val_kernel(const float* __restrict__ nodes,
                                const float* __restrict__ w_val,
                                const float* __restrict__ b_val)
{
    __shared__ float feat[16][132];
    __shared__ float ws[64][132];
    int t = threadIdx.x;
    int row0 = blockIdx.x * 16;

    for (int idx = t; idx < 16 * 32; idx += 256) {
        int r = idx >> 5, d4 = idx & 31;
        *(float4*)&feat[r][d4 * 4] = ((const float4*)(nodes + (row0 + r) * 128))[d4];
    }
    __syncthreads();

    int o_local = t & 63;
    int rbase   = (t >> 6) * 4;

    for (int c = 0; c < 48; c++) {
        int o0 = c * 64;
        for (int idx = t; idx < 64 * 32; idx += 256) {
            int oo = idx >> 5, d4 = idx & 31;
            *(float4*)&ws[oo][d4 * 4] = ((const float4*)(w_val + (o0 + oo) * 128))[d4];
        }
        __syncthreads();

        float a0 = 0.f, a1 = 0.f, a2 = 0.f, a3 = 0.f;
        #pragma unroll 4
        for (int d4 = 0; d4 < 32; d4++) {
            float4 w  = *(float4*)&ws[o_local][d4 * 4];
            float4 f0 = *(float4*)&feat[rbase + 0][d4 * 4];
            float4 f1 = *(float4*)&feat[rbase + 1][d4 * 4];
            float4 f2 = *(float4*)&feat[rbase + 2][d4 * 4];
            float4 f3 = *(float4*)&feat[rbase + 3][d4 * 4];
            a0 += w.x*f0.x + w.y*f0.y + w.z*f0.z + w.w*f0.w;
            a1 += w.x*f1.x + w.y*f1.y + w.z*f1.z + w.w*f1.w;
            a2 += w.x*f2.x + w.y*f2.y + w.z*f2.z + w.w*f2.w;
            a3 += w.x*f3.x + w.y*f3.y + w.z*f3.z + w.w*f3.w;
        }
        int og = o0 + o_local;
        float bb = b_val[og];
        int jp = (row0 + rbase) >> 1;      // rbase multiple of 4 -> pair aligned
        g_valp[(size_t)jp * VSTR + og]       = __floats2half2_rn(a0 + bb, a1 + bb);
        g_valp[(size_t)(jp + 1) * VSTR + og] = __floats2half2_rn(a2 + bb, a3 + bb);
        __syncthreads();
    }
}

// ============================================================================
// Kernel 3: flash attention, fp16 m16n8k16 mma, cp.async double buffering.
// grid = (24, 32), block = 256 (8 warps). Warp: 16 i-rows x 64 d-cols.
// MMA1 uses fp16 hi/lo 2-split (3 terms, lo*lo dropped ~2^-22) == 3xTF32 class.
// ============================================================================
__global__ void __launch_bounds__(256) flash_head_mma_kernel()
{
    __shared__ float  sp  [64][36];       // fp32 logits
    __shared__ __half sph [64][40];       // fp16 probabilities (MMA2 A operand)
    __shared__ float  sm_[64], sl_[64], sfac_[64];
    __shared__ __half sqh [2][32][40];    // q hi, stride 40 halves (80B, 16B-mult)
    __shared__ __half sql [2][32][40];    // q lo
    __shared__ __half2 svp[2][16][136];   // v j-pairs, stride 136 h2 (conflict-free)

    const int t    = threadIdx.x;
    const int lane = t & 31;
    const int w    = t >> 5;
    const int gid  = lane >> 2;
    const int tig  = lane & 3;
    const int iw   = w >> 1;
    const int dblk = w & 1;

    const int h  = blockIdx.x;
    const int i0 = blockIdx.y * 64;
    const bool rot_head = (h >= 16);

    // staging coordinates: qh/ql 128 16B-chunks each, svp 512 chunks
    const int q_row = (t & 127) >> 2, q_ch = t & 3;
    const bool do_qh = (t < 128);

    // ---- prologue: stage tile 0 into buffer 0 ----
    {
        const __half* qsrc = do_qh ? g_qh16 : g_ql16;
        uint32_t qdst = (uint32_t)__cvta_generic_to_shared(
            do_qh ? &sqh[0][q_row][q_ch * 8] : &sql[0][q_row][q_ch * 8]);
        cpa16(qdst, qsrc + (size_t)q_row * KQSTR + h * CD + q_ch * 8);
        #pragma unroll
        for (int k = 0; k < 2; k++) {
            int ch = t + k * 256;
            int pr = ch >> 5, c8 = ch & 31;
            cpa16((uint32_t)__cvta_generic_to_shared(&svp[0][pr][c8 * 4]),
                  g_valp + (size_t)pr * VSTR + h * ND + c8 * 4);
        }
        cpa_commit();
    }

    // ---- K fragments (hi/lo) direct from global, reused across all tiles ----
    uint32_t kh[2][4], kl[2][4];
    {
        int r0 = i0 + iw * 16 + gid, r1 = r0 + 8;
        #pragma unroll
        for (int ks = 0; ks < 2; ks++) {
            int c0 = h * CD + ks * 16 + 2 * tig;
            kh[ks][0] = *(const uint32_t*)&g_kh16[(size_t)r0 * KQSTR + c0];
            kh[ks][1] = *(const uint32_t*)&g_kh16[(size_t)r1 * KQSTR + c0];
            kh[ks][2] = *(const uint32_t*)&g_kh16[(size_t)r0 * KQSTR + c0 + 8];
            kh[ks][3] = *(const uint32_t*)&g_kh16[(size_t)r1 * KQSTR + c0 + 8];
            kl[ks][0] = *(const uint32_t*)&g_kl16[(size_t)r0 * KQSTR + c0];
            kl[ks][1] = *(const uint32_t*)&g_kl16[(size_t)r1 * KQSTR + c0];
            kl[ks][2] = *(const uint32_t*)&g_kl16[(size_t)r0 * KQSTR + c0 + 8];
            kl[ks][3] = *(const uint32_t*)&g_kl16[(size_t)r1 * KQSTR + c0 + 8];
        }
    }
    if (t < 64) { sm_[t] = -1.0e30f; sl_[t] = 0.f; }

    float acc[8][4];
    #pragma unroll
    for (int nt = 0; nt < 8; nt++)
        #pragma unroll
        for (int r = 0; r < 4; r++) acc[nt][r] = 0.f;

    for (int tile = 0; tile < 64; tile++) {
        cpa_wait0();
        __syncthreads();
        const int buf = tile & 1;

        // prefetch next tile
        if (tile + 1 < 64) {
            int j1 = (tile + 1) * 32;
            int nb = buf ^ 1;
            const __half* qsrc = do_qh ? g_qh16 : g_ql16;
            uint32_t qdst = (uint32_t)__cvta_generic_to_shared(
                do_qh ? &sqh[nb][q_row][q_ch * 8] : &sql[nb][q_row][q_ch * 8]);
            cpa16(qdst, qsrc + (size_t)(j1 + q_row) * KQSTR + h * CD + q_ch * 8);
            #pragma unroll
            for (int k = 0; k < 2; k++) {
                int ch = t + k * 256;
                int pr = ch >> 5, c8 = ch & 31;
                cpa16((uint32_t)__cvta_generic_to_shared(&svp[nb][pr][c8 * 4]),
                      g_valp + (size_t)(j1 / 2 + pr) * VSTR + h * ND + c8 * 4);
            }
            cpa_commit();
        }

        // ---- MMA1: S[64x32] = K @ Q^T, 3-term fp16 split ----
        #pragma unroll
        for (int s = 0; s < 2; s++) {
            int jb = dblk * 2 + s;
            float d[4] = {0.f, 0.f, 0.f, 0.f};
            #pragma unroll
            for (int ks = 0; ks < 2; ks++) {
                const __half* qr = &sqh[buf][jb * 8 + gid][ks * 16 + 2 * tig];
                const __half* lr = &sql[buf][jb * 8 + gid][ks * 16 + 2 * tig];
                uint32_t bh0 = *(const uint32_t*)qr;
                uint32_t bh1 = *(const uint32_t*)(qr + 8);
                uint32_t bl0 = *(const uint32_t*)lr;
                uint32_t bl1 = *(const uint32_t*)(lr + 8);
                mma_f16(d, kh[ks][0], kh[ks][1], kh[ks][2], kh[ks][3], bh0, bh1);
                mma_f16(d, kh[ks][0], kh[ks][1], kh[ks][2], kh[ks][3], bl0, bl1);
                mma_f16(d, kl[ks][0], kl[ks][1], kl[ks][2], kl[ks][3], bh0, bh1);
            }
            int ri = iw * 16 + gid;
            int co = jb * 8 + 2 * tig;
            *(float2*)&sp[ri    ][co] = make_float2(d[0], d[1]);
            *(float2*)&sp[ri + 8][co] = make_float2(d[2], d[3]);
        }
        __syncthreads();

        // ---- online softmax: thread t -> row t>>2, 8 cols ----
        {
            int row = t >> 2;
            int c0  = (t & 3) * 8;
            float4 e0 = *(float4*)&sp[row][c0];
            float4 e1 = *(float4*)&sp[row][c0 + 4];
            if (rot_head) {
                e0.x *= e0.x; e0.y *= e0.y; e0.z *= e0.z; e0.w *= e0.w;
                e1.x *= e1.x; e1.y *= e1.y; e1.z *= e1.z; e1.w *= e1.w;
            }
            float mx8 = fmaxf(fmaxf(fmaxf(e0.x, e0.y), fmaxf(e0.z, e0.w)),
                              fmaxf(fmaxf(e1.x, e1.y), fmaxf(e1.z, e1.w)));
            mx8 = fmaxf(mx8, __shfl_xor_sync(0xffffffffu, mx8, 1));
            mx8 = fmaxf(mx8, __shfl_xor_sync(0xffffffffu, mx8, 2));
            float mo = sm_[row];
            float mx = fmaxf(mo, mx8);
            float p0 = __expf(e0.x - mx), p1 = __expf(e0.y - mx);
            float p2 = __expf(e0.z - mx), p3 = __expf(e0.w - mx);
            float p4 = __expf(e1.x - mx), p5 = __expf(e1.y - mx);
            float p6 = __expf(e1.z - mx), p7 = __expf(e1.w - mx);
            float sum = ((p0 + p1) + (p2 + p3)) + ((p4 + p5) + (p6 + p7));
            *(__half2*)&sph[row][c0    ] = __floats2half2_rn(p0, p1);
            *(__half2*)&sph[row][c0 + 2] = __floats2half2_rn(p2, p3);
            *(__half2*)&sph[row][c0 + 4] = __floats2half2_rn(p4, p5);
            *(__half2*)&sph[row][c0 + 6] = __floats2half2_rn(p6, p7);
            sum += __shfl_xor_sync(0xffffffffu, sum, 1);
            sum += __shfl_xor_sync(0xffffffffu, sum, 2);
            if ((t & 3) == 0) {
                float fac = __expf(mo - mx);
                sl_[row]   = sl_[row] * fac + sum;
                sm_[row]   = mx;
                sfac_[row] = fac;
            }
        }
        __syncthreads();

        // ---- rescale accumulators ----
        {
            float f0 = sfac_[iw * 16 + gid];
            float f1 = sfac_[iw * 16 + gid + 8];
            #pragma unroll
            for (int nt = 0; nt < 8; nt++) {
                acc[nt][0] *= f0; acc[nt][1] *= f0;
                acc[nt][2] *= f1; acc[nt][3] *= f1;
            }
        }

        // ---- MMA2: out[16x64] += P[16x32] @ V[32x64] (fp16) ----
        #pragma unroll
        for (int ks = 0; ks < 2; ks++) {
            const __half* pa = &sph[iw * 16 + gid][ks * 16 + 2 * tig];
            uint32_t a0 = *(const uint32_t*)pa;
            uint32_t a1 = *(const uint32_t*)(pa + 8 * 40);
            uint32_t a2 = *(const uint32_t*)(pa + 8);
            uint32_t a3 = *(const uint32_t*)(pa + 8 * 40 + 8);
            const __half2* v0 = &svp[buf][ks * 8 + tig    ][dblk * 64 + gid];
            const __half2* v1 = &svp[buf][ks * 8 + tig + 4][dblk * 64 + gid];
            #pragma unroll
            for (int nt = 0; nt < 8; nt++) {
                uint32_t b0 = *(const uint32_t*)&v0[nt * 8];
                uint32_t b1 = *(const uint32_t*)&v1[nt * 8];
                mma_f16(acc[nt], a0, a1, a2, a3, b0, b1);
            }
        }
        // buffer-reuse hazards covered by top-of-loop wait+sync
    }

    // ---- epilogue: normalize, write per-head partial ----
    {
        int r0 = iw * 16 + gid;
        int r1 = r0 + 8;
        float rl0 = 1.f / sl_[r0];
        float rl1 = 1.f / sl_[r1];
        #pragma unroll
        for (int nt = 0; nt < 8; nt++) {
            int col = dblk * 64 + nt * 8 + 2 * tig;
            float2 v0 = make_float2(acc[nt][0] * rl0, acc[nt][1] * rl0);
            float2 v1 = make_float2(acc[nt][2] * rl1, acc[nt][3] * rl1);
            *(float2*)&g_part[((size_t)h * SEQ + i0 + r0) * ND + col] = v0;
            *(float2*)&g_part[((size_t)h * SEQ + i0 + r1) * ND + col] = v1;
        }
    }
}

// ============================================================================
// Kernel 4: sum 24 head partials -> out [2048, 128]
// ============================================================================
__global__ void reduce_kernel(float* __restrict__ out)
{
    int idx = blockIdx.x * 256 + threadIdx.x;
    float s = 0.f;
    #pragma unroll
    for (int h = 0; h < NH; h++)
        s += g_part[(size_t)h * (SEQ * ND) + idx];
    out[idx] = s;
}

// ============================================================================
extern "C" void kernel_launch(void* const* d_in, const int* in_sizes, int n_in,
                              void* d_out, int out_size)
{
    const float* nodes = (const float*)d_in[0];
    const float* pos   = (const float*)d_in[1];
    const float* rot   = (const float*)d_in[2];
    const float* w_nkq = (const float*)d_in[3];
    const float* b_nkq = (const float*)d_in[4];
    const float* w_pkq = (const float*)d_in[5];
    const float* b_pkq = (const float*)d_in[6];
    const float* w_rkq = (const float*)d_in[7];
    const float* w_val = (const float*)d_in[8];
    const float* b_val = (const float*)d_in[9];
    float* out = (float*)d_out;

    proj_kq_kernel<<<SEQ / 16, 256>>>(nodes, pos, rot, w_nkq, b_nkq,
                                      w_pkq, b_pkq, w_rkq);
    proj_val_kernel<<<SEQ / 16, 256>>>(nodes, w_val, b_val);
    dim3 g3(NH, SEQ / 64);
    flash_head_mma_kernel<<<g3, 256>>>();
    reduce_kernel<<<(SEQ * ND) / 256, 256>>>(out);
}